// round 13
// baseline (speedup 1.0000x reference)
#include <cuda_runtime.h>
#include <cuda_bf16.h>
#include <mma.h>
#include <float.h>
#include <stdint.h>

using namespace nvcuda;

#define N_NODES 50000
#define N_PAD   50048
#define N_EDGES 640000
#define D       128
#define OUTF    128
#define TM      128
#define LDS_K   48
#define NBLK    49              // scan blocks of 1024 (49*1024 >= N_NODES)

// ---------------- device scratch ----------------
__device__ __align__(16) float g_h[N_PAD * D];
__device__ __align__(16) float g_neigh[N_NODES * D];
__device__ int   g_deg[N_NODES];
__device__ int   g_start[N_NODES + 1];
__device__ int   g_cursor[N_NODES];
__device__ int   g_part[NBLK];
__device__ __align__(16) int2 g_edge[N_EDGES];   // packed (src, weight-bits)

__device__ __forceinline__ int clampN(int v) { return min(max(v, 0), N_NODES - 1); }

// ---------------- CSR build ----------------
__global__ void zero_deg_kernel() {
    int i = blockIdx.x * blockDim.x + threadIdx.x;
    if (i < N_NODES) g_deg[i] = 0;
}

__global__ void hist_kernel(const int* __restrict__ dst) {
    int e = blockIdx.x * blockDim.x + threadIdx.x;
    if (e < N_EDGES) atomicAdd(&g_deg[clampN(dst[e])], 1);
}

// scan p1: per-block (1024) partial sums
__global__ __launch_bounds__(1024) void scan_p1() {
    int t = threadIdx.x, idx = blockIdx.x * 1024 + t;
    int v = (idx < N_NODES) ? g_deg[idx] : 0;
    #pragma unroll
    for (int off = 16; off > 0; off >>= 1) v += __shfl_down_sync(0xFFFFFFFFu, v, off);
    __shared__ int sh[32];
    if ((t & 31) == 0) sh[t >> 5] = v;
    __syncthreads();
    if (t < 32) {
        int x = sh[t];
        #pragma unroll
        for (int off = 16; off > 0; off >>= 1) x += __shfl_down_sync(0xFFFFFFFFu, x, off);
        if (t == 0) g_part[blockIdx.x] = x;
    }
}

// scan p3 (p2 folded in): warp 0 sums partials < b; block scan + offset
__global__ __launch_bounds__(1024) void scan_p3() {
    __shared__ int sh[1024];
    __shared__ int s_boff;
    int b = blockIdx.x, t = threadIdx.x, idx = b * 1024 + t;
    if (t < 32) {
        int acc = 0;
        for (int j = t; j < b; j += 32) acc += g_part[j];   // b <= 48: <=2 loads/lane
        #pragma unroll
        for (int off = 16; off > 0; off >>= 1) acc += __shfl_down_sync(0xFFFFFFFFu, acc, off);
        if (t == 0) s_boff = acc;
    }
    int v = (idx < N_NODES) ? g_deg[idx] : 0;
    sh[t] = v;
    __syncthreads();
    #pragma unroll
    for (int off = 1; off < 1024; off <<= 1) {
        int x = (t >= off) ? sh[t - off] : 0;
        __syncthreads();
        sh[t] += x;
        __syncthreads();
    }
    int excl = sh[t] - v + s_boff;
    if (idx < N_NODES) { g_start[idx] = excl; g_cursor[idx] = excl; }
    if (idx == N_NODES - 1) g_start[N_NODES] = excl + v;
}

__global__ void scatter_kernel(const int* __restrict__ src, const int* __restrict__ dst,
                               const float* __restrict__ weight) {
    int e = blockIdx.x * blockDim.x + threadIdx.x;
    if (e >= N_EDGES) return;
    int d = clampN(dst[e]);
    int pos = atomicAdd(&g_cursor[d], 1);
    g_edge[pos] = make_int2(clampN(src[e]), __float_as_int(weight[e]));
}

// ---------------- warp-per-node max reduce, float4 gather, int2 edge loads ----------------
__global__ __launch_bounds__(256) void reduce_kernel() {
    const int node = (blockIdx.x << 3) + (threadIdx.x >> 5);
    const int lane = threadIdx.x & 31;
    if (node >= N_NODES) return;
    const int beg = g_start[node], end = g_start[node + 1];
    const int col = lane * 4;
    float4 acc = make_float4(-FLT_MAX, -FLT_MAX, -FLT_MAX, -FLT_MAX);
    int i = beg;
    for (; i + 4 <= end; i += 4) {
        int2 e0 = g_edge[i],   e1 = g_edge[i+1], e2 = g_edge[i+2], e3 = g_edge[i+3];
        float w0 = __int_as_float(e0.y), w1 = __int_as_float(e1.y);
        float w2 = __int_as_float(e2.y), w3 = __int_as_float(e3.y);
        float4 v0 = *(const float4*)&g_h[e0.x*D + col];
        float4 v1 = *(const float4*)&g_h[e1.x*D + col];
        float4 v2 = *(const float4*)&g_h[e2.x*D + col];
        float4 v3 = *(const float4*)&g_h[e3.x*D + col];
        acc.x = fmaxf(acc.x, v0.x*w0); acc.y = fmaxf(acc.y, v0.y*w0);
        acc.z = fmaxf(acc.z, v0.z*w0); acc.w = fmaxf(acc.w, v0.w*w0);
        acc.x = fmaxf(acc.x, v1.x*w1); acc.y = fmaxf(acc.y, v1.y*w1);
        acc.z = fmaxf(acc.z, v1.z*w1); acc.w = fmaxf(acc.w, v1.w*w1);
        acc.x = fmaxf(acc.x, v2.x*w2); acc.y = fmaxf(acc.y, v2.y*w2);
        acc.z = fmaxf(acc.z, v2.z*w2); acc.w = fmaxf(acc.w, v2.w*w2);
        acc.x = fmaxf(acc.x, v3.x*w3); acc.y = fmaxf(acc.y, v3.y*w3);
        acc.z = fmaxf(acc.z, v3.z*w3); acc.w = fmaxf(acc.w, v3.w*w3);
    }
    for (; i < end; i++) {
        int2 e = g_edge[i];
        float w = __int_as_float(e.y);
        float4 v = *(const float4*)&g_h[e.x*D + col];
        acc.x = fmaxf(acc.x, v.x*w); acc.y = fmaxf(acc.y, v.y*w);
        acc.z = fmaxf(acc.z, v.z*w); acc.w = fmaxf(acc.w, v.w*w);
    }
    float4 outv = (beg == end) ? make_float4(0.f, 0.f, 0.f, 0.f) : acc;
    *(float4*)&g_neigh[node*D + col] = outv;
}

// ---------------- wmma bf16 3-pass GEMM, K=128 (R12-verbatim) ----------------
static constexpr int SM_REG   = 128 * LDS_K;
static constexpr int SM_F_OFF = 4 * SM_REG * 2;
static constexpr int SMEM_SZ  = SM_F_OFF + 16 * 128 * 4;

template<bool A_NEIGH, int WSTR, bool TO_GH, bool ACCUM>
__global__ __launch_bounds__(256) void gemm_wmma_kernel(const float* __restrict__ A0,
                                                        const float* __restrict__ W,
                                                        const float* __restrict__ bias,
                                                        float* __restrict__ outp) {
    extern __shared__ char smem[];
    __nv_bfloat16* sAhi = (__nv_bfloat16*)smem;
    __nv_bfloat16* sAlo = sAhi + SM_REG;
    __nv_bfloat16* sBhi = sAlo + SM_REG;
    __nv_bfloat16* sBlo = sBhi + SM_REG;
    float*         sF   = (float*)(smem + SM_F_OFF);

    const int tid  = threadIdx.x;
    const int lane = tid & 31;
    const int wid  = tid >> 5;
    const int wm   = wid >> 1;
    const int wn   = wid & 1;
    const int row0 = blockIdx.x * TM;

    float* dstp = TO_GH ? g_h : outp;                 // device symbol ref (shadow-ptr trap!)
    const float* Asrc = A_NEIGH ? (const float*)g_neigh : A0;

    wmma::fragment<wmma::accumulator, 16, 16, 16, float> acc[2][4];
    if (!ACCUM) {
        for (int i = tid; i < 16 * 128; i += 256) sF[i] = bias[i & 127];
        __syncthreads();
        #pragma unroll
        for (int mt = 0; mt < 2; mt++)
            #pragma unroll
            for (int nt = 0; nt < 4; nt++)
                wmma::load_matrix_sync(acc[mt][nt], sF + wn * 64 + nt * 16, 128, wmma::mem_row_major);
        __syncthreads();
    } else {
        #pragma unroll
        for (int mt = 0; mt < 2; mt++) {
            int r0 = row0 + wm * 32 + mt * 16;
            #pragma unroll
            for (int nt = 0; nt < 4; nt++) {
                int c0 = wn * 64 + nt * 16;
                if (r0 + 16 <= N_NODES) {
                    wmma::load_matrix_sync(acc[mt][nt], &outp[r0 * OUTF + c0], OUTF, wmma::mem_row_major);
                } else {
                    float* st = sF + wid * 256;
                    for (int i = lane; i < 256; i += 32) {
                        int rr = min(r0 + (i >> 4), N_NODES - 1);
                        st[i] = outp[rr * OUTF + c0 + (i & 15)];
                    }
                    __syncwarp();
                    wmma::load_matrix_sync(acc[mt][nt], st, 16, wmma::mem_row_major);
                    __syncwarp();
                }
            }
        }
        __syncthreads();
    }

    for (int c = 0; c < 4; c++) {
        const int k0 = c * 32;
        if (c > 0) __syncthreads();

        #pragma unroll
        for (int t = 0; t < 4; t++) {
            int g = tid + t * 256;
            int row = g >> 3, kc = (g & 7) * 4;
            int grow = row0 + row;
            float4 v = (grow < N_NODES) ? *(const float4*)&Asrc[grow * D + k0 + kc]
                                        : make_float4(0.f, 0.f, 0.f, 0.f);
            __nv_bfloat16 h0 = __float2bfloat16_rn(v.x), h1 = __float2bfloat16_rn(v.y);
            __nv_bfloat16 h2 = __float2bfloat16_rn(v.z), h3 = __float2bfloat16_rn(v.w);
            __nv_bfloat16 l0 = __float2bfloat16_rn(v.x - __bfloat162float(h0));
            __nv_bfloat16 l1 = __float2bfloat16_rn(v.y - __bfloat162float(h1));
            __nv_bfloat16 l2 = __float2bfloat16_rn(v.z - __bfloat162float(h2));
            __nv_bfloat16 l3 = __float2bfloat16_rn(v.w - __bfloat162float(h3));
            int o = row * LDS_K + kc;
            *(__nv_bfloat162*)&sAhi[o]     = __nv_bfloat162(h0, h1);
            *(__nv_bfloat162*)&sAhi[o + 2] = __nv_bfloat162(h2, h3);
            *(__nv_bfloat162*)&sAlo[o]     = __nv_bfloat162(l0, l1);
            *(__nv_bfloat162*)&sAlo[o + 2] = __nv_bfloat162(l2, l3);
        }
        #pragma unroll
        for (int t = 0; t < 4; t++) {
            int g = tid + t * 256;
            int row = g >> 3, kc = (g & 7) * 4;
            float4 v = *(const float4*)&W[row * WSTR + k0 + kc];
            __nv_bfloat16 h0 = __float2bfloat16_rn(v.x), h1 = __float2bfloat16_rn(v.y);
            __nv_bfloat16 h2 = __float2bfloat16_rn(v.z), h3 = __float2bfloat16_rn(v.w);
            __nv_bfloat16 l0 = __float2bfloat16_rn(v.x - __bfloat162float(h0));
            __nv_bfloat16 l1 = __float2bfloat16_rn(v.y - __bfloat162float(h1));
            __nv_bfloat16 l2 = __float2bfloat16_rn(v.z - __bfloat162float(h2));
            __nv_bfloat16 l3 = __float2bfloat16_rn(v.w - __bfloat162float(h3));
            int o = row * LDS_K + kc;
            *(__nv_bfloat162*)&sBhi[o]     = __nv_bfloat162(h0, h1);
            *(__nv_bfloat162*)&sBhi[o + 2] = __nv_bfloat162(h2, h3);
            *(__nv_bfloat162*)&sBlo[o]     = __nv_bfloat162(l0, l1);
            *(__nv_bfloat162*)&sBlo[o + 2] = __nv_bfloat162(l2, l3);
        }
        __syncthreads();

        #pragma unroll
        for (int ks = 0; ks < 2; ks++) {
            const int k16 = ks * 16;
            wmma::fragment<wmma::matrix_a, 16, 16, 16, __nv_bfloat16, wmma::row_major> ahi[2], alo[2];
            #pragma unroll
            for (int mt = 0; mt < 2; mt++) {
                int r = wm * 32 + mt * 16;
                wmma::load_matrix_sync(ahi[mt], &sAhi[r * LDS_K + k16], LDS_K);
                wmma::load_matrix_sync(alo[mt], &sAlo[r * LDS_K + k16], LDS_K);
            }
            #pragma unroll
            for (int nt = 0; nt < 4; nt++) {
                int n = wn * 64 + nt * 16;
                wmma::fragment<wmma::matrix_b, 16, 16, 16, __nv_bfloat16, wmma::col_major> bhi, blo;
                wmma::load_matrix_sync(bhi, &sBhi[n * LDS_K + k16], LDS_K);
                wmma::load_matrix_sync(blo, &sBlo[n * LDS_K + k16], LDS_K);
                #pragma unroll
                for (int mt = 0; mt < 2; mt++) {
                    wmma::mma_sync(acc[mt][nt], ahi[mt], bhi, acc[mt][nt]);
                    wmma::mma_sync(acc[mt][nt], alo[mt], bhi, acc[mt][nt]);
                    wmma::mma_sync(acc[mt][nt], ahi[mt], blo, acc[mt][nt]);
                }
            }
        }
    }

    __syncthreads();
    #pragma unroll
    for (int mt = 0; mt < 2; mt++) {
        int r0 = row0 + wm * 32 + mt * 16;
        #pragma unroll
        for (int nt = 0; nt < 4; nt++) {
            int c0 = wn * 64 + nt * 16;
            if (TO_GH || r0 + 16 <= N_NODES) {
                wmma::store_matrix_sync(&dstp[r0 * OUTF + c0], acc[mt][nt], OUTF, wmma::mem_row_major);
            } else {
                float* st = sF + wid * 256;
                wmma::store_matrix_sync(st, acc[mt][nt], 16, wmma::mem_row_major);
                __syncwarp();
                for (int i = lane; i < 256; i += 32) {
                    int rr = r0 + (i >> 4);
                    if (rr < N_NODES) dstp[rr * OUTF + c0 + (i & 15)] = st[i];
                }
                __syncwarp();
            }
        }
    }
}

// ---------------- launch ----------------
extern "C" void kernel_launch(void* const* d_in, const int* in_sizes, int n_in,
                              void* d_out, int out_size) {
    const float* feat    = (const float*)d_in[0];
    const float* weight  = (const float*)d_in[1];
    const int*   src     = (const int*)d_in[2];
    const int*   dst     = (const int*)d_in[3];
    const float* W_pool  = (const float*)d_in[4];
    const float* b_pool  = (const float*)d_in[5];
    const float* W_neigh = (const float*)d_in[6];
    const float* b_neigh = (const float*)d_in[7];
    float*       out     = (float*)d_out;

    cudaFuncSetAttribute(gemm_wmma_kernel<false, 128, true,  false>,
                         cudaFuncAttributeMaxDynamicSharedMemorySize, SMEM_SZ);
    cudaFuncSetAttribute(gemm_wmma_kernel<false, 256, false, false>,
                         cudaFuncAttributeMaxDynamicSharedMemorySize, SMEM_SZ);
    cudaFuncSetAttribute(gemm_wmma_kernel<true,  256, false, true>,
                         cudaFuncAttributeMaxDynamicSharedMemorySize, SMEM_SZ);

    const int GEMM_GRID = (N_NODES + TM - 1) / TM;   // 391

    cudaStream_t aux;
    cudaStreamCreate(&aux);
    cudaEvent_t evFork, evJ1, evJ2;
    cudaEventCreateWithFlags(&evFork, cudaEventDisableTiming);
    cudaEventCreateWithFlags(&evJ1,   cudaEventDisableTiming);
    cudaEventCreateWithFlags(&evJ2,   cudaEventDisableTiming);

    cudaEventRecord(evFork, 0);
    cudaStreamWaitEvent(aux, evFork, 0);

    // main: CSR build chain
    zero_deg_kernel<<<(N_NODES + 255) / 256, 256>>>();
    hist_kernel<<<(N_EDGES + 255) / 256, 256>>>(dst);
    scan_p1<<<NBLK, 1024>>>();
    scan_p3<<<NBLK, 1024>>>();
    scatter_kernel<<<(N_EDGES + 255) / 256, 256>>>(src, dst, weight);

    // aux: gemm1 (-> g_h), then gemm2a (feat half of fc_neigh -> out partial)
    gemm_wmma_kernel<false, 128, true, false><<<GEMM_GRID, 256, SMEM_SZ, aux>>>(feat, W_pool, b_pool, nullptr);
    cudaEventRecord(evJ1, aux);
    gemm_wmma_kernel<false, 256, false, false><<<GEMM_GRID, 256, SMEM_SZ, aux>>>(feat, W_neigh, b_neigh, out);
    cudaEventRecord(evJ2, aux);

    // main: reduce needs scatter (main) + gemm1 (evJ1)
    cudaStreamWaitEvent(0, evJ1, 0);
    reduce_kernel<<<(N_NODES + 7) / 8, 256>>>();

    // main: gemm2b needs reduce (main) + gemm2a (evJ2); accumulates into out
    cudaStreamWaitEvent(0, evJ2, 0);
    gemm_wmma_kernel<true, 256, false, true><<<GEMM_GRID, 256, SMEM_SZ>>>(nullptr, W_neigh + D, b_neigh, out);
}